// round 15
// baseline (speedup 1.0000x reference)
#include <cuda_runtime.h>
#include <cuda_fp16.h>
#include <cstdint>

// ---------------------------------------------------------------------------
// GraphSAGE 2-layer, N=100000, E=1600000, 128 -> 128 -> 64.
//   layer1: h1 = relu( mean_agg(x) @ Wl1 + x @ Wr1 + b1 )
//   layer2: out = mean_agg(h1 @ Wl2) + h1 @ Wr2 + b2   (agg is linear)
// Graph-forked pipeline:
//   default: prehist -> scan_scatter -> agg16 -> fused2 -> final16
//   side s1: gemmr (xr = x @ Wr1), forked after prehist, joined before fused2
// gemmr overlaps the CSR build + aggregation (complementary pipes).
// NOTE: tcgen05 unavailable (harness compiles PTX at compute_100).
// ---------------------------------------------------------------------------

#define NNODES_MAX 100000
#define EDGES_MAX  1600000
#define SCAN_BLK   1024

__device__ int     d_deg[NNODES_MAX + 1];     // zeroed by k_final16 for replay
__device__ int     d_rowptr[NNODES_MAX + 1];
__device__ int     d_cur[NNODES_MAX + 1];
__device__ int     d_bsums[128];              // zeroed by k_final16
__device__ int     d_bflag[128];              // zeroed by k_final16
__device__ int     d_barrier;                 // zeroed by k_final16
__device__ int     d_adj[EDGES_MAX];
__device__ __align__(16) __half   d_x16[(size_t)NNODES_MAX * 128];
__device__ __align__(16) __half   d_agg16[(size_t)NNODES_MAX * 128];
__device__ __align__(16) uint32_t d_wl1c[128 * 64];  // Wl1 [n][k2] half2, K=128
__device__ __align__(16) uint32_t d_wr1c[128 * 64];  // Wr1 [n][k2] half2, K=128
__device__ __align__(16) uint32_t d_w2c[128 * 64];   // W2  [n][k2] half2, K=128
__device__ __align__(16) uint32_t d_xr16[(size_t)NNODES_MAX * 64]; // xr k-paired fp16
__device__ __align__(16) __half   d_p16[(size_t)NNODES_MAX * 64];
__device__ __align__(16) float    d_q[(size_t)NNODES_MAX * 64];

// int32 edge arrays have random nonzero odd 32-bit words; int64 (<2^31) no.
__device__ __forceinline__ int detect_not64_block(const void* ei) {
    __shared__ int s_not64;
    if (threadIdx.x == 0) {
        const unsigned int* w = (const unsigned int*)ei;
        unsigned int o = 0;
#pragma unroll
        for (int j = 1; j < 32; j += 2) o |= w[j];
        s_not64 = (o != 0);
    }
    __syncthreads();
    return s_not64;
}

// ---------------------------------------------------------------------------
// 1) x -> fp16; Wl1/Wr1/W2 -> fp16 k-paired col-major; degree histogram
// ---------------------------------------------------------------------------

__global__ void k_prehist(const float* __restrict__ x, const void* __restrict__ ei,
                          const float* __restrict__ W1l, const float* __restrict__ W1r,
                          const float* __restrict__ W2l, const float* __restrict__ W2r,
                          int n, int E) {
    int not64 = detect_not64_block(ei);
    int i = blockIdx.x * blockDim.x + threadIdx.x;
    if (i < n * 32) {                          // one float4 -> uint2 per thread
        float4 v = __ldg((const float4*)x + i);
        __half2 h0 = __floats2half2_rn(v.x, v.y);
        __half2 h1 = __floats2half2_rn(v.z, v.w);
        uint2 u;
        u.x = *(const unsigned int*)&h0;
        u.y = *(const unsigned int*)&h1;
        ((uint2*)d_x16)[i] = u;
    }
    if (i < E) {
        int dst = not64 ? ((const int*)ei)[E + i]
                        : (int)((const long long*)ei)[(size_t)E + i];
        atomicAdd(&d_deg[dst], 1);
    }
    // weight images: [n=128][k2=64] half2 (k = 2*k2)
    if (i < 128 * 64) {
        int nn = i >> 6, k = (i & 63) * 2;
        __half2 h = __floats2half2_rn(W1l[k * 128 + nn], W1l[(k + 1) * 128 + nn]);
        d_wl1c[i] = *(const uint32_t*)&h;
    } else if (i < 2 * 128 * 64) {
        int j = i - 128 * 64;
        int nn = j >> 6, k = (j & 63) * 2;
        __half2 h = __floats2half2_rn(W1r[k * 128 + nn], W1r[(k + 1) * 128 + nn]);
        d_wr1c[j] = *(const uint32_t*)&h;
    } else if (i < 3 * 128 * 64) {
        int j = i - 2 * 128 * 64;
        int nn = j >> 6, k = (j & 63) * 2;
        float f0, f1;
        if (nn < 64) { f0 = W2l[k * 64 + nn]; f1 = W2l[(k + 1) * 64 + nn]; }
        else         { f0 = W2r[k * 64 + (nn - 64)]; f1 = W2r[(k + 1) * 64 + (nn - 64)]; }
        __half2 h = __floats2half2_rn(f0, f1);
        d_w2c[j] = *(const uint32_t*)&h;
    }
}

// ---------------------------------------------------------------------------
// 2) lookback scan over block sums + grid barrier + CSR scatter
// ---------------------------------------------------------------------------

__global__ void k_scan_scatter(const void* __restrict__ ei, int n, int E) {
    int not64 = detect_not64_block(ei);
    __shared__ int wsum[32];
    __shared__ int s_off;
    int b = blockIdx.x;
    int i = b * SCAN_BLK + threadIdx.x;
    int v = (i < n) ? d_deg[i] : 0;
    int lane = threadIdx.x & 31, w = threadIdx.x >> 5;
    int inc = v;
#pragma unroll
    for (int o = 1; o < 32; o <<= 1) {
        int t = __shfl_up_sync(0xffffffffu, inc, o);
        if (lane >= o) inc += t;
    }
    if (lane == 31) wsum[w] = inc;
    __syncthreads();
    if (w == 0) {
        int s = wsum[lane];
        int si = s;
#pragma unroll
        for (int o = 1; o < 32; o <<= 1) {
            int t = __shfl_up_sync(0xffffffffu, si, o);
            if (lane >= o) si += t;
        }
        wsum[lane] = si - s;
    }
    __syncthreads();
    int excl = inc - v + wsum[w];

    if (threadIdx.x == SCAN_BLK - 1) {
        d_bsums[b] = excl + v;
        __threadfence();
        *((volatile int*)&d_bflag[b]) = 1;
    }
    if (w == 0) {
        int sum = 0;
        for (int j = lane; j < b; j += 32) {
            while (*((volatile int*)&d_bflag[j]) == 0) __nanosleep(50);
            sum += *((volatile int*)&d_bsums[j]);
        }
#pragma unroll
        for (int o = 16; o > 0; o >>= 1) sum += __shfl_down_sync(0xffffffffu, sum, o);
        if (lane == 0) s_off = sum;
    }
    __syncthreads();
    if (i < n) {
        int t = excl + s_off;
        d_rowptr[i] = t;
        d_cur[i] = t;
    }

    __syncthreads();
    if (threadIdx.x == 0) {
        __threadfence();
        atomicAdd(&d_barrier, 1);
        while (*((volatile int*)&d_barrier) < gridDim.x) __nanosleep(100);
    }
    __syncthreads();

    int stride = gridDim.x * blockDim.x;
    for (int e = b * SCAN_BLK + threadIdx.x; e < E; e += stride) {
        int src, dst;
        if (not64) {
            const int* p = (const int*)ei;
            src = p[e];
            dst = p[E + e];
        } else {
            const long long* p = (const long long*)ei;
            src = (int)p[e];
            dst = (int)p[(size_t)E + e];
        }
        int pos = atomicAdd(&d_cur[dst], 1);
        d_adj[pos] = src;
    }
}

// ---------------------------------------------------------------------------
// 3) layer-1 aggregation: warp/node, fp16 feats, depth-2 hadd2 trees
// ---------------------------------------------------------------------------

#define H2(v) (*(const __half2*)&(v))

__global__ void k_agg16(int n) {
    int gw = (blockIdx.x * blockDim.x + threadIdx.x) >> 5;
    if (gw >= n) return;
    int lane = threadIdx.x & 31;
    int start = d_rowptr[gw], deg = d_deg[gw];
    const uint2* base = (const uint2*)d_x16;
    float ax = 0.f, ay = 0.f, az = 0.f, aw = 0.f;
    int j = 0;
    for (; j + 8 <= deg; j += 8) {
        int idx[8];
#pragma unroll
        for (int q = 0; q < 8; q++) idx[q] = d_adj[start + j + q];
        uint2 u[8];
#pragma unroll
        for (int q = 0; q < 8; q++) u[q] = __ldg(base + (size_t)idx[q] * 32 + lane);
#pragma unroll
        for (int p = 0; p < 2; p++) {
            const uint2* g = u + p * 4;
            __half2 sx = __hadd2(__hadd2(H2(g[0].x), H2(g[1].x)),
                                 __hadd2(H2(g[2].x), H2(g[3].x)));
            __half2 sy = __hadd2(__hadd2(H2(g[0].y), H2(g[1].y)),
                                 __hadd2(H2(g[2].y), H2(g[3].y)));
            float2 f0 = __half22float2(sx);
            float2 f1 = __half22float2(sy);
            ax += f0.x; ay += f0.y; az += f1.x; aw += f1.y;
        }
    }
    for (; j + 4 <= deg; j += 4) {
        uint2 g[4];
#pragma unroll
        for (int q = 0; q < 4; q++)
            g[q] = __ldg(base + (size_t)d_adj[start + j + q] * 32 + lane);
        __half2 sx = __hadd2(__hadd2(H2(g[0].x), H2(g[1].x)),
                             __hadd2(H2(g[2].x), H2(g[3].x)));
        __half2 sy = __hadd2(__hadd2(H2(g[0].y), H2(g[1].y)),
                             __hadd2(H2(g[2].y), H2(g[3].y)));
        float2 f0 = __half22float2(sx);
        float2 f1 = __half22float2(sy);
        ax += f0.x; ay += f0.y; az += f1.x; aw += f1.y;
    }
    for (; j + 2 <= deg; j += 2) {
        int na = d_adj[start + j], nb = d_adj[start + j + 1];
        uint2 ua = __ldg(base + (size_t)na * 32 + lane);
        uint2 ub = __ldg(base + (size_t)nb * 32 + lane);
        __half2 s0 = __hadd2(H2(ua.x), H2(ub.x));
        __half2 s1 = __hadd2(H2(ua.y), H2(ub.y));
        float2 f0 = __half22float2(s0);
        float2 f1 = __half22float2(s1);
        ax += f0.x; ay += f0.y; az += f1.x; aw += f1.y;
    }
    if (j < deg) {
        int nb = d_adj[start + j];
        uint2 u = __ldg(base + (size_t)nb * 32 + lane);
        float2 f0 = __half22float2(H2(u.x));
        float2 f1 = __half22float2(H2(u.y));
        ax += f0.x; ay += f0.y; az += f1.x; aw += f1.y;
    }
    float inv = 1.0f / (float)(deg > 0 ? deg : 1);
    __half2 h0 = __floats2half2_rn(ax * inv, ay * inv);
    __half2 h1 = __floats2half2_rn(az * inv, aw * inv);
    uint2 u;
    u.x = *(const unsigned int*)&h0;
    u.y = *(const unsigned int*)&h1;
    ((uint2*)d_agg16)[(size_t)gw * 32 + lane] = u;
}

// ---------------------------------------------------------------------------
// 6) out = mean_agg(p16) + q + b2 ; resets device state for next replay
// ---------------------------------------------------------------------------

__global__ void k_final16(float* __restrict__ out, const float* __restrict__ b2, int n) {
    int gw = (blockIdx.x * blockDim.x + threadIdx.x) >> 5;
    if (gw >= n) return;
    int lane = threadIdx.x & 31;
    int start = d_rowptr[gw], deg = d_deg[gw];
    const unsigned int* base = (const unsigned int*)d_p16;
    float ax = 0.f, ay = 0.f;
    int j = 0;
    for (; j + 8 <= deg; j += 8) {
        int idx[8];
#pragma unroll
        for (int q = 0; q < 8; q++) idx[q] = d_adj[start + j + q];
        unsigned int u[8];
#pragma unroll
        for (int q = 0; q < 8; q++) u[q] = __ldg(base + (size_t)idx[q] * 32 + lane);
#pragma unroll
        for (int p = 0; p < 2; p++) {
            const unsigned int* g = u + p * 4;
            __half2 s = __hadd2(__hadd2(H2(g[0]), H2(g[1])),
                                __hadd2(H2(g[2]), H2(g[3])));
            float2 f = __half22float2(s);
            ax += f.x; ay += f.y;
        }
    }
    for (; j + 4 <= deg; j += 4) {
        unsigned int g[4];
#pragma unroll
        for (int q = 0; q < 4; q++)
            g[q] = __ldg(base + (size_t)d_adj[start + j + q] * 32 + lane);
        __half2 s = __hadd2(__hadd2(H2(g[0]), H2(g[1])),
                            __hadd2(H2(g[2]), H2(g[3])));
        float2 f = __half22float2(s);
        ax += f.x; ay += f.y;
    }
    for (; j + 2 <= deg; j += 2) {
        int na = d_adj[start + j], nb = d_adj[start + j + 1];
        unsigned int ua = __ldg(base + (size_t)na * 32 + lane);
        unsigned int ub = __ldg(base + (size_t)nb * 32 + lane);
        __half2 s = __hadd2(H2(ua), H2(ub));
        float2 f = __half22float2(s);
        ax += f.x; ay += f.y;
    }
    if (j < deg) {
        int nb = d_adj[start + j];
        unsigned int u = __ldg(base + (size_t)nb * 32 + lane);
        float2 f = __half22float2(H2(u));
        ax += f.x; ay += f.y;
    }
    float inv = 1.0f / (float)(deg > 0 ? deg : 1);
    float2 q = *(const float2*)(d_q + (size_t)gw * 64 + 2 * lane);
    float2 bb = *(const float2*)(b2 + 2 * lane);
    float2 r;
    r.x = ax * inv + q.x + bb.x;
    r.y = ay * inv + q.y + bb.y;
    *(float2*)(out + (size_t)gw * 64 + 2 * lane) = r;

    if (lane == 0) d_deg[gw] = 0;
    if (blockIdx.x == 0 && threadIdx.x < 128) {
        d_bsums[threadIdx.x] = 0;
        d_bflag[threadIdx.x] = 0;
        if (threadIdx.x == 0) d_barrier = 0;
    }
}

// ---------------------------------------------------------------------------
// mma.sync GEMM common pieces (R12-winning structure)
// ---------------------------------------------------------------------------

#define AST   20
#define BST   20
#define A2ST  68
#define STGB  20480
#define BOFF  10240
#define A2_B  61440
#define SMEM_F2  (A2_B + 128 * A2ST * 4)   // 96256 (k_fused2)
#define SMEM_GR  61440                      // k_gemmr (no A2)

__device__ __forceinline__ void mma_f16(float c[4],
                                        uint32_t a0, uint32_t a1, uint32_t a2, uint32_t a3,
                                        uint32_t b0, uint32_t b1) {
    asm volatile(
        "mma.sync.aligned.m16n8k16.row.col.f32.f16.f16.f32 "
        "{%0,%1,%2,%3},{%4,%5,%6,%7},{%8,%9},{%0,%1,%2,%3};"
        : "+f"(c[0]), "+f"(c[1]), "+f"(c[2]), "+f"(c[3])
        : "r"(a0), "r"(a1), "r"(a2), "r"(a3), "r"(b0), "r"(b1));
}

__device__ __forceinline__ void ldsm_x4(uint32_t& r0, uint32_t& r1,
                                        uint32_t& r2, uint32_t& r3, uint32_t addr) {
    asm volatile("ldmatrix.sync.aligned.m8n8.x4.shared.b16 {%0,%1,%2,%3}, [%4];"
                 : "=r"(r0), "=r"(r1), "=r"(r2), "=r"(r3) : "r"(addr));
}

__device__ __forceinline__ void cp16(uint32_t dst, const void* src, int sz) {
    asm volatile("cp.async.cg.shared.global [%0], [%1], 16, %2;"
                 :: "r"(dst), "l"(src), "r"(sz) : "memory");
}
#define CP_COMMIT() asm volatile("cp.async.commit_group;" ::: "memory")
#define CP_WAIT0()  asm volatile("cp.async.wait_group 0;" ::: "memory")
#define CP_WAIT1()  asm volatile("cp.async.wait_group 1;" ::: "memory")

// ---------------------------------------------------------------------------
// 2b) k_gemmr: xr = x @ Wr1 (K=128, 4 ktiles) -> fp16 k-paired d_xr16.
//     Runs on a side stream, overlapped with CSR build + aggregation.
// ---------------------------------------------------------------------------

__global__ __launch_bounds__(512, 2) void k_gemmr(int M) {
    extern __shared__ uint32_t smem[];
    const uint32_t sb = (uint32_t)__cvta_generic_to_shared(smem);
    const int tid = threadIdx.x;
    const int lane = tid & 31;
    const int warp = tid >> 5;
    const int wm = warp >> 2, wn = warp & 3;
    const int g = lane >> 2, t = lane & 3;
    const int row0 = blockIdx.x * 128;

    const int arow = lane & 15;
    const int acolw = (lane >> 4) * 4;
    const int brow = (lane & 7) + ((lane >= 16) ? 8 : 0);
    const int bcolw = ((lane & 15) >= 8) ? 4 : 0;

    const int ldrow = tid >> 2, ldc4 = tid & 3;
    const int grow = row0 + ldrow;
    const int avalid = (grow < M) ? 16 : 0;
    const size_t arowoff = (size_t)((grow < M) ? grow : 0) * 16;

    const uint4* x4 = (const uint4*)d_x16;
    const uint4* wr = (const uint4*)d_wr1c;    // 16 uint4 per n

    const uint32_t a_dst = sb + (uint32_t)(ldrow * AST + ldc4 * 4) * 4;
    const uint32_t b_dst = sb + BOFF + (uint32_t)(ldrow * BST + ldc4 * 4) * 4;

    float acc[2][4][4];
#pragma unroll
    for (int mi = 0; mi < 2; mi++)
#pragma unroll
        for (int ni = 0; ni < 4; ni++)
#pragma unroll
            for (int r = 0; r < 4; r++) acc[mi][ni][r] = 0.f;

    auto mma_tiles = [&](uint32_t aBase, uint32_t bBase) {
#pragma unroll
        for (int ks = 0; ks < 2; ks++) {
            uint32_t a[2][4];
#pragma unroll
            for (int mi = 0; mi < 2; mi++) {
                uint32_t addr = aBase +
                    (uint32_t)(((wm * 32 + mi * 16 + arow) * AST) + ks * 8 + acolw) * 4;
                ldsm_x4(a[mi][0], a[mi][1], a[mi][2], a[mi][3], addr);
            }
            uint32_t bf[2][4];
#pragma unroll
            for (int pr = 0; pr < 2; pr++) {
                uint32_t addr = bBase +
                    (uint32_t)(((wn * 32 + pr * 16 + brow) * BST) + ks * 8 + bcolw) * 4;
                ldsm_x4(bf[pr][0], bf[pr][1], bf[pr][2], bf[pr][3], addr);
            }
#pragma unroll
            for (int mi = 0; mi < 2; mi++)
#pragma unroll
                for (int ni = 0; ni < 4; ni++)
                    mma_f16(acc[mi][ni], a[mi][0], a[mi][1], a[mi][2], a[mi][3],
                            bf[ni >> 1][(ni & 1) * 2], bf[ni >> 1][(ni & 1) * 2 + 1]);
        }
    };

    auto loadA = [&](int kt, uint32_t stg) {
        cp16(a_dst + stg * STGB, x4 + arowoff + kt * 4 + ldc4, avalid);
    };
    auto loadB = [&](int kt, uint32_t stg) {
        cp16(b_dst + stg * STGB, wr + ldrow * 16 + kt * 4 + ldc4, 16);
    };

    loadA(0, 0); loadB(0, 0); CP_COMMIT();
    loadA(1, 1); loadB(1, 1); CP_COMMIT();
#pragma unroll
    for (int kt = 0; kt < 4; kt++) {
        if (kt < 3) CP_WAIT1(); else CP_WAIT0();
        __syncthreads();
        if (kt + 2 < 4) { loadA(kt + 2, (kt + 2) % 3); loadB(kt + 2, (kt + 2) % 3); CP_COMMIT(); }
        const uint32_t s = (kt % 3) * STGB;
        mma_tiles(sb + s, sb + BOFF + s);
    }

    // epilogue: xr -> fp16 k-paired [row][64 uint]
#pragma unroll
    for (int mi = 0; mi < 2; mi++) {
#pragma unroll
        for (int ni = 0; ni < 4; ni++) {
            int r0 = row0 + wm * 32 + mi * 16 + g;
            int ci = (wn * 32 + ni * 8 + 2 * t) >> 1;
            __half2 h0 = __floats2half2_rn(acc[mi][ni][0], acc[mi][ni][1]);
            __half2 h1 = __floats2half2_rn(acc[mi][ni][2], acc[mi][ni][3]);
            if (r0 < M)     d_xr16[(size_t)r0 * 64 + ci] = *(const uint32_t*)&h0;
            if (r0 + 8 < M) d_xr16[(size_t)(r0 + 8) * 64 + ci] = *(const uint32_t*)&h1;
        }
    }
}

// ---------------------------------------------------------------------------
// 5) k_fused2: phase1 acc = agg16 @ Wl1 (K=128); h1 = relu(acc + xr + b1)
//    -> fp16 smem A2; phase2 [p|q] = h1 @ W2 (K=128).
// ---------------------------------------------------------------------------

__global__ __launch_bounds__(512, 2) void k_fused2(const float* __restrict__ b1, int M) {
    extern __shared__ uint32_t smem[];
    const uint32_t sb = (uint32_t)__cvta_generic_to_shared(smem);
    const int tid = threadIdx.x;
    const int lane = tid & 31;
    const int warp = tid >> 5;
    const int wm = warp >> 2, wn = warp & 3;
    const int g = lane >> 2, t = lane & 3;
    const int row0 = blockIdx.x * 128;

    const int arow = lane & 15;
    const int acolw = (lane >> 4) * 4;
    const int brow = (lane & 7) + ((lane >= 16) ? 8 : 0);
    const int bcolw = ((lane & 15) >= 8) ? 4 : 0;

    const int ldrow = tid >> 2, ldc4 = tid & 3;
    const int grow = row0 + ldrow;
    const int avalid = (grow < M) ? 16 : 0;
    const size_t arowoff = (size_t)((grow < M) ? grow : 0) * 16;

    const uint4* agg4 = (const uint4*)d_agg16;
    const uint4* wl   = (const uint4*)d_wl1c;  // 16 uint4 per n
    const uint4* w2   = (const uint4*)d_w2c;   // 16 uint4 per n

    const uint32_t a_dst = sb + (uint32_t)(ldrow * AST + ldc4 * 4) * 4;
    const uint32_t b_dst = sb + BOFF + (uint32_t)(ldrow * BST + ldc4 * 4) * 4;

    float acc[2][4][4];
#pragma unroll
    for (int mi = 0; mi < 2; mi++)
#pragma unroll
        for (int ni = 0; ni < 4; ni++)
#pragma unroll
            for (int r = 0; r < 4; r++) acc[mi][ni][r] = 0.f;

    auto mma_tiles = [&](uint32_t aBase, int astride, int kof, uint32_t bBase) {
#pragma unroll
        for (int ks = 0; ks < 2; ks++) {
            uint32_t a[2][4];
#pragma unroll
            for (int mi = 0; mi < 2; mi++) {
                uint32_t addr = aBase +
                    (uint32_t)(((wm * 32 + mi * 16 + arow) * astride) +
                               kof + ks * 8 + acolw) * 4;
                ldsm_x4(a[mi][0], a[mi][1], a[mi][2], a[mi][3], addr);
            }
            uint32_t bf[2][4];
#pragma unroll
            for (int pr = 0; pr < 2; pr++) {
                uint32_t addr = bBase +
                    (uint32_t)(((wn * 32 + pr * 16 + brow) * BST) + ks * 8 + bcolw) * 4;
                ldsm_x4(bf[pr][0], bf[pr][1], bf[pr][2], bf[pr][3], addr);
            }
#pragma unroll
            for (int mi = 0; mi < 2; mi++)
#pragma unroll
                for (int ni = 0; ni < 4; ni++)
                    mma_f16(acc[mi][ni], a[mi][0], a[mi][1], a[mi][2], a[mi][3],
                            bf[ni >> 1][(ni & 1) * 2], bf[ni >> 1][(ni & 1) * 2 + 1]);
        }
    };

    auto loadA1 = [&](int kt, uint32_t stg) {
        cp16(a_dst + stg * STGB, agg4 + arowoff + kt * 4 + ldc4, avalid);
    };
    auto loadB1 = [&](int kt, uint32_t stg) {
        cp16(b_dst + stg * STGB, wl + ldrow * 16 + kt * 4 + ldc4, 16);
    };
    auto loadB2 = [&](int kt, uint32_t stg) {
        cp16(b_dst + stg * STGB, w2 + ldrow * 16 + kt * 4 + ldc4, 16);
    };

    // ----- phase 1: K = 128, 4 ktiles -----
    loadA1(0, 0); loadB1(0, 0); CP_COMMIT();
    loadA1(1, 1); loadB1(1, 1); CP_COMMIT();
#pragma unroll
    for (int kt = 0; kt < 4; kt++) {
        if (kt < 3) CP_WAIT1(); else CP_WAIT0();
        __syncthreads();
        if (kt + 2 < 4) { loadA1(kt + 2, (kt + 2) % 3); loadB1(kt + 2, (kt + 2) % 3); CP_COMMIT(); }
        const uint32_t s = (kt % 3) * STGB;
        mma_tiles(sb + s, AST, 0, sb + BOFF + s);
    }

    __syncthreads();

    // prefetch W2 ktiles 0,1 (overlaps epilogue)
    loadB2(0, 0); CP_COMMIT();
    loadB2(1, 1); CP_COMMIT();

    // phase-1 epilogue: h1 = relu(acc + xr + b1) -> fp16 A2 (k-paired)
    {
        uint32_t* A2w = smem + A2_B / 4;
#pragma unroll
        for (int mi = 0; mi < 2; mi++) {
#pragma unroll
            for (int ni = 0; ni < 4; ni++) {
                int rr = wm * 32 + mi * 16 + g;
                int cc = wn * 32 + ni * 8 + 2 * t;
                int ci = cc >> 1;
                int r0 = row0 + rr;
                float bb0 = b1[cc], bb1 = b1[cc + 1];
                uint32_t xu0 = (r0 < M) ? __ldg(d_xr16 + (size_t)r0 * 64 + ci) : 0u;
                uint32_t xu1 = (r0 + 8 < M) ? __ldg(d_xr16 + (size_t)(r0 + 8) * 64 + ci) : 0u;
                float2 xf0 = __half22float2(H2(xu0));
                float2 xf1 = __half22float2(H2(xu1));
                __half2 h0 = __floats2half2_rn(
                    fmaxf(acc[mi][ni][0] + xf0.x + bb0, 0.f),
                    fmaxf(acc[mi][ni][1] + xf0.y + bb1, 0.f));
                __half2 h1 = __floats2half2_rn(
                    fmaxf(acc[mi][ni][2] + xf1.x + bb0, 0.f),
                    fmaxf(acc[mi][ni][3] + xf1.y + bb1, 0.f));
                A2w[rr * A2ST + ci] = *(const uint32_t*)&h0;
                A2w[(rr + 8) * A2ST + ci] = *(const uint32_t*)&h1;
            }
        }
    }
#pragma unroll
    for (int mi = 0; mi < 2; mi++)
#pragma unroll
        for (int ni = 0; ni < 4; ni++)
#pragma unroll
            for (int r = 0; r < 4; r++) acc[mi][ni][r] = 0.f;

    // ----- phase 2: K = 128, 4 ktiles, A2 resident -----
#pragma unroll
    for (int kt = 0; kt < 4; kt++) {
        if (kt < 3) CP_WAIT1(); else CP_WAIT0();
        __syncthreads();                     // also orders A2 writes (kt==0)
        if (kt + 2 < 4) { loadB2(kt + 2, (kt + 2) % 3); CP_COMMIT(); }
        mma_tiles(sb + A2_B, A2ST, kt * 16, sb + BOFF + (kt % 3) * STGB);
    }

    // phase-2 epilogue: cols < 64 -> p fp16; cols >= 64 -> q fp32
#pragma unroll
    for (int mi = 0; mi < 2; mi++) {
#pragma unroll
        for (int ni = 0; ni < 4; ni++) {
            int r0 = row0 + wm * 32 + mi * 16 + g;
            int cc = wn * 32 + ni * 8 + 2 * t;
            if (cc < 64) {
                __half2 h0 = __floats2half2_rn(acc[mi][ni][0], acc[mi][ni][1]);
                __half2 h1 = __floats2half2_rn(acc[mi][ni][2], acc[mi][ni][3]);
                if (r0 < M)
                    *(__half2*)(d_p16 + (size_t)r0 * 64 + cc) = h0;
                if (r0 + 8 < M)
                    *(__half2*)(d_p16 + (size_t)(r0 + 8) * 64 + cc) = h1;
            } else {
                int cq = cc - 64;
                if (r0 < M)
                    *(float2*)(d_q + (size_t)r0 * 64 + cq) =
                        make_float2(acc[mi][ni][0], acc[mi][ni][1]);
                if (r0 + 8 < M)
                    *(float2*)(d_q + (size_t)(r0 + 8) * 64 + cq) =
                        make_float2(acc[mi][ni][2], acc[mi][ni][3]);
            }
        }
    }
}

// ---------------------------------------------------------------------------
// Launch (graph fork/join: gemmr overlaps scan_scatter + agg16)
// ---------------------------------------------------------------------------

extern "C" void kernel_launch(void* const* d_in, const int* in_sizes, int n_in,
                              void* d_out, int out_size) {
    const float* x   = (const float*)d_in[0];
    const void*  ei  = d_in[1];
    const float* Wl1 = (const float*)d_in[2];
    const float* Wr1 = (const float*)d_in[3];
    const float* b1  = (const float*)d_in[4];
    const float* Wl2 = (const float*)d_in[5];
    const float* Wr2 = (const float*)d_in[6];
    const float* b2  = (const float*)d_in[7];
    float* out = (float*)d_out;

    int n = in_sizes[0] / 128;
    int E = in_sizes[1] / 2;

    static cudaStream_t s1;
    static cudaEvent_t e0, e1;
    static int inited = 0;
    if (!inited) {
        cudaFuncSetAttribute(k_fused2, cudaFuncAttributeMaxDynamicSharedMemorySize,
                             SMEM_F2);
        cudaFuncSetAttribute(k_gemmr, cudaFuncAttributeMaxDynamicSharedMemorySize,
                             SMEM_GR);
        cudaStreamCreateWithFlags(&s1, cudaStreamNonBlocking);
        cudaEventCreateWithFlags(&e0, cudaEventDisableTiming);
        cudaEventCreateWithFlags(&e1, cudaEventDisableTiming);
        inited = 1;
    }

    int nb = (n + SCAN_BLK - 1) / SCAN_BLK;
    int ngrid = (n + 127) / 128;

    k_prehist<<<(n * 32 + 255) / 256, 256>>>(x, ei, Wl1, Wr1, Wl2, Wr2, n, E);

    // fork: xr = x @ Wr1 on side stream (overlaps CSR build + aggregation)
    cudaEventRecord(e0, 0);
    cudaStreamWaitEvent(s1, e0, 0);
    k_gemmr<<<ngrid, 512, SMEM_GR, s1>>>(n);
    cudaEventRecord(e1, s1);

    k_scan_scatter<<<nb, SCAN_BLK>>>(ei, n, E);
    k_agg16<<<(n * 32 + 255) / 256, 256>>>(n);

    // join before the fused GEMM consumes xr
    cudaStreamWaitEvent(0, e1, 0);
    k_fused2<<<ngrid, 512, SMEM_F2>>>(b1, n);
    k_final16<<<(n * 32 + 255) / 256, 256>>>(out, b2, n);
}

// round 16
// speedup vs baseline: 1.0960x; 1.0960x over previous
#include <cuda_runtime.h>
#include <cuda_fp16.h>
#include <cstdint>

// ---------------------------------------------------------------------------
// GraphSAGE 2-layer, N=100000, E=1600000, 128 -> 128 -> 64.
//   layer1: h1 = relu( mean_agg(x) @ Wl1 + x @ Wr1 + b1 )
//   layer2: out = mean_agg(h1 @ Wl2) + h1 @ Wr2 + b2   (agg is linear)
// 5 launches:
//   1 k_prehist      x->fp16, W->fp16 k-paired transposed, degree histogram
//                    (captures per-edge rank from the histogram atomic)
//   2 k_scan_scatter lookback scan + grid barrier + atomic-free CSR scatter
//   3 k_agg16        fp16 warp-gather mean agg (depth-2 hadd2 trees)
//   4 k_fused        fp16 m16n8k16 GEMM, 512 thr, 3-stage cp.async (1 sync/kt)
//   5 k_final16      fp16 gather + residual + bias (+ reset state for replay)
// NOTE: tcgen05 unavailable (harness compiles PTX at compute_100).
// ---------------------------------------------------------------------------

#define NNODES_MAX 100000
#define EDGES_MAX  1600000
#define SCAN_BLK   1024

__device__ int     d_deg[NNODES_MAX + 1];     // zeroed by k_final16 for replay
__device__ int     d_rowptr[NNODES_MAX + 1];
__device__ int     d_erank[EDGES_MAX];        // per-edge rank within dst
__device__ int     d_bsums[128];              // zeroed by k_final16
__device__ int     d_bflag[128];              // zeroed by k_final16
__device__ int     d_barrier;                 // zeroed by k_final16
__device__ int     d_adj[EDGES_MAX];
__device__ __align__(16) __half   d_x16[(size_t)NNODES_MAX * 128];
__device__ __align__(16) __half   d_agg16[(size_t)NNODES_MAX * 128];
__device__ __align__(16) uint32_t d_w1c[128 * 128];  // [n][k2] half2, K=256
__device__ __align__(16) uint32_t d_w2c[128 * 64];   // [n][k2] half2, K=128
__device__ __align__(16) __half   d_p16[(size_t)NNODES_MAX * 64];
__device__ __align__(16) float    d_q[(size_t)NNODES_MAX * 64];

// int32 edge arrays have random nonzero odd 32-bit words; int64 (<2^31) no.
__device__ __forceinline__ int detect_not64_block(const void* ei) {
    __shared__ int s_not64;
    if (threadIdx.x == 0) {
        const unsigned int* w = (const unsigned int*)ei;
        unsigned int o = 0;
#pragma unroll
        for (int j = 1; j < 32; j += 2) o |= w[j];
        s_not64 = (o != 0);
    }
    __syncthreads();
    return s_not64;
}

// ---------------------------------------------------------------------------
// 1) x -> fp16; W1/W2 -> fp16 k-paired col-major; degree histogram.
//    The histogram atomic's return value IS the edge's rank within its
//    destination node — store it so the scatter needs no atomics.
// ---------------------------------------------------------------------------

__global__ void k_prehist(const float* __restrict__ x, const void* __restrict__ ei,
                          const float* __restrict__ W1l, const float* __restrict__ W1r,
                          const float* __restrict__ W2l, const float* __restrict__ W2r,
                          int n, int E) {
    int not64 = detect_not64_block(ei);
    int i = blockIdx.x * blockDim.x + threadIdx.x;
    if (i < n * 32) {                          // one float4 -> uint2 per thread
        float4 v = __ldg((const float4*)x + i);
        __half2 h0 = __floats2half2_rn(v.x, v.y);
        __half2 h1 = __floats2half2_rn(v.z, v.w);
        uint2 u;
        u.x = *(const unsigned int*)&h0;
        u.y = *(const unsigned int*)&h1;
        ((uint2*)d_x16)[i] = u;
    }
    if (i < E) {
        int dst = not64 ? ((const int*)ei)[E + i]
                        : (int)((const long long*)ei)[(size_t)E + i];
        d_erank[i] = atomicAdd(&d_deg[dst], 1);
    }
    // W1c: [n=128][k2=128], k = 2*k2; k<128 from W1l, else W1r
    if (i < 128 * 128) {
        int nn = i >> 7, k2 = i & 127, k = k2 * 2;
        float f0, f1;
        if (k < 128) { f0 = W1l[k * 128 + nn]; f1 = W1l[(k + 1) * 128 + nn]; }
        else         { f0 = W1r[(k - 128) * 128 + nn]; f1 = W1r[(k - 127) * 128 + nn]; }
        __half2 h = __floats2half2_rn(f0, f1);
        d_w1c[i] = *(const uint32_t*)&h;
    } else if (i < 128 * 128 + 128 * 64) {
        // W2c: [n=128][k2=64]; n<64 from W2l, else W2r
        int j = i - 128 * 128;
        int nn = j >> 6, k2 = j & 63, k = k2 * 2;
        float f0, f1;
        if (nn < 64) { f0 = W2l[k * 64 + nn]; f1 = W2l[(k + 1) * 64 + nn]; }
        else         { f0 = W2r[k * 64 + (nn - 64)]; f1 = W2r[(k + 1) * 64 + (nn - 64)]; }
        __half2 h = __floats2half2_rn(f0, f1);
        d_w2c[j] = *(const uint32_t*)&h;
    }
}

// ---------------------------------------------------------------------------
// 2) lookback scan over block sums + grid barrier + atomic-free CSR scatter
//    (98 blocks, all resident -> spins are deadlock-free)
// ---------------------------------------------------------------------------

__global__ void k_scan_scatter(const void* __restrict__ ei, int n, int E) {
    int not64 = detect_not64_block(ei);
    __shared__ int wsum[32];
    __shared__ int s_off;
    int b = blockIdx.x;
    int i = b * SCAN_BLK + threadIdx.x;
    int v = (i < n) ? d_deg[i] : 0;
    int lane = threadIdx.x & 31, w = threadIdx.x >> 5;
    int inc = v;
#pragma unroll
    for (int o = 1; o < 32; o <<= 1) {
        int t = __shfl_up_sync(0xffffffffu, inc, o);
        if (lane >= o) inc += t;
    }
    if (lane == 31) wsum[w] = inc;
    __syncthreads();
    if (w == 0) {
        int s = wsum[lane];
        int si = s;
#pragma unroll
        for (int o = 1; o < 32; o <<= 1) {
            int t = __shfl_up_sync(0xffffffffu, si, o);
            if (lane >= o) si += t;
        }
        wsum[lane] = si - s;
    }
    __syncthreads();
    int excl = inc - v + wsum[w];

    if (threadIdx.x == SCAN_BLK - 1) {
        d_bsums[b] = excl + v;
        __threadfence();
        *((volatile int*)&d_bflag[b]) = 1;
    }
    if (w == 0) {
        int sum = 0;
        for (int j = lane; j < b; j += 32) {
            while (*((volatile int*)&d_bflag[j]) == 0) __nanosleep(50);
            sum += *((volatile int*)&d_bsums[j]);
        }
#pragma unroll
        for (int o = 16; o > 0; o >>= 1) sum += __shfl_down_sync(0xffffffffu, sum, o);
        if (lane == 0) s_off = sum;
    }
    __syncthreads();
    if (i < n) d_rowptr[i] = excl + s_off;

    // grid barrier: all rowptr[] must be written before any scatter
    __syncthreads();
    if (threadIdx.x == 0) {
        __threadfence();
        atomicAdd(&d_barrier, 1);
        while (*((volatile int*)&d_barrier) < gridDim.x) __nanosleep(100);
    }
    __syncthreads();

    int stride = gridDim.x * blockDim.x;
    for (int e = b * SCAN_BLK + threadIdx.x; e < E; e += stride) {
        int src, dst;
        if (not64) {
            const int* p = (const int*)ei;
            src = p[e];
            dst = p[E + e];
        } else {
            const long long* p = (const long long*)ei;
            src = (int)p[e];
            dst = (int)p[(size_t)E + e];
        }
        d_adj[d_rowptr[dst] + d_erank[e]] = src;
    }
}

// ---------------------------------------------------------------------------
// 3) layer-1 aggregation: warp/node, fp16 feats, depth-2 hadd2 trees,
//    fp32 accumulate, fp16 out
// ---------------------------------------------------------------------------

#define H2(v) (*(const __half2*)&(v))

__global__ void k_agg16(int n) {
    int gw = (blockIdx.x * blockDim.x + threadIdx.x) >> 5;
    if (gw >= n) return;
    int lane = threadIdx.x & 31;
    int start = d_rowptr[gw], deg = d_deg[gw];
    const uint2* base = (const uint2*)d_x16;    // 32 uint2 per 128-half row
    float ax = 0.f, ay = 0.f, az = 0.f, aw = 0.f;
    int j = 0;
    for (; j + 8 <= deg; j += 8) {
        int idx[8];
#pragma unroll
        for (int q = 0; q < 8; q++) idx[q] = d_adj[start + j + q];
        uint2 u[8];
#pragma unroll
        for (int q = 0; q < 8; q++) u[q] = __ldg(base + (size_t)idx[q] * 32 + lane);
#pragma unroll
        for (int p = 0; p < 2; p++) {
            const uint2* g = u + p * 4;
            __half2 sx = __hadd2(__hadd2(H2(g[0].x), H2(g[1].x)),
                                 __hadd2(H2(g[2].x), H2(g[3].x)));
            __half2 sy = __hadd2(__hadd2(H2(g[0].y), H2(g[1].y)),
                                 __hadd2(H2(g[2].y), H2(g[3].y)));
            float2 f0 = __half22float2(sx);
            float2 f1 = __half22float2(sy);
            ax += f0.x; ay += f0.y; az += f1.x; aw += f1.y;
        }
    }
    for (; j + 4 <= deg; j += 4) {
        uint2 g[4];
#pragma unroll
        for (int q = 0; q < 4; q++)
            g[q] = __ldg(base + (size_t)d_adj[start + j + q] * 32 + lane);
        __half2 sx = __hadd2(__hadd2(H2(g[0].x), H2(g[1].x)),
                             __hadd2(H2(g[2].x), H2(g[3].x)));
        __half2 sy = __hadd2(__hadd2(H2(g[0].y), H2(g[1].y)),
                             __hadd2(H2(g[2].y), H2(g[3].y)));
        float2 f0 = __half22float2(sx);
        float2 f1 = __half22float2(sy);
        ax += f0.x; ay += f0.y; az += f1.x; aw += f1.y;
    }
    for (; j + 2 <= deg; j += 2) {
        int na = d_adj[start + j], nb = d_adj[start + j + 1];
        uint2 ua = __ldg(base + (size_t)na * 32 + lane);
        uint2 ub = __ldg(base + (size_t)nb * 32 + lane);
        __half2 s0 = __hadd2(H2(ua.x), H2(ub.x));
        __half2 s1 = __hadd2(H2(ua.y), H2(ub.y));
        float2 f0 = __half22float2(s0);
        float2 f1 = __half22float2(s1);
        ax += f0.x; ay += f0.y; az += f1.x; aw += f1.y;
    }
    if (j < deg) {
        int nb = d_adj[start + j];
        uint2 u = __ldg(base + (size_t)nb * 32 + lane);
        float2 f0 = __half22float2(H2(u.x));
        float2 f1 = __half22float2(H2(u.y));
        ax += f0.x; ay += f0.y; az += f1.x; aw += f1.y;
    }
    float inv = 1.0f / (float)(deg > 0 ? deg : 1);
    __half2 h0 = __floats2half2_rn(ax * inv, ay * inv);
    __half2 h1 = __floats2half2_rn(az * inv, aw * inv);
    uint2 u;
    u.x = *(const unsigned int*)&h0;
    u.y = *(const unsigned int*)&h1;
    ((uint2*)d_agg16)[(size_t)gw * 32 + lane] = u;
}

// ---------------------------------------------------------------------------
// 5) out = mean_agg(p16) + q + b2 ; resets device state for next replay
// ---------------------------------------------------------------------------

__global__ void k_final16(float* __restrict__ out, const float* __restrict__ b2, int n) {
    int gw = (blockIdx.x * blockDim.x + threadIdx.x) >> 5;
    if (gw >= n) return;
    int lane = threadIdx.x & 31;
    int start = d_rowptr[gw], deg = d_deg[gw];
    const unsigned int* base = (const unsigned int*)d_p16;  // 32 uints per row
    float ax = 0.f, ay = 0.f;
    int j = 0;
    for (; j + 8 <= deg; j += 8) {
        int idx[8];
#pragma unroll
        for (int q = 0; q < 8; q++) idx[q] = d_adj[start + j + q];
        unsigned int u[8];
#pragma unroll
        for (int q = 0; q < 8; q++) u[q] = __ldg(base + (size_t)idx[q] * 32 + lane);
#pragma unroll
        for (int p = 0; p < 2; p++) {
            const unsigned int* g = u + p * 4;
            __half2 s = __hadd2(__hadd2(H2(g[0]), H2(g[1])),
                                __hadd2(H2(g[2]), H2(g[3])));
            float2 f = __half22float2(s);
            ax += f.x; ay += f.y;
        }
    }
    for (; j + 4 <= deg; j += 4) {
        unsigned int g[4];
#pragma unroll
        for (int q = 0; q < 4; q++)
            g[q] = __ldg(base + (size_t)d_adj[start + j + q] * 32 + lane);
        __half2 s = __hadd2(__hadd2(H2(g[0]), H2(g[1])),
                            __hadd2(H2(g[2]), H2(g[3])));
        float2 f = __half22float2(s);
        ax += f.x; ay += f.y;
    }
    for (; j + 2 <= deg; j += 2) {
        int na = d_adj[start + j], nb = d_adj[start + j + 1];
        unsigned int ua = __ldg(base + (size_t)na * 32 + lane);
        unsigned int ub = __ldg(base + (size_t)nb * 32 + lane);
        __half2 s = __hadd2(H2(ua), H2(ub));
        float2 f = __half22float2(s);
        ax += f.x; ay += f.y;
    }
    if (j < deg) {
        int nb = d_adj[start + j];
        unsigned int u = __ldg(base + (size_t)nb * 32 + lane);
        float2 f = __half22float2(H2(u));
        ax += f.x; ay += f.y;
    }
    float inv = 1.0f / (float)(deg > 0 ? deg : 1);
    float2 q = *(const float2*)(d_q + (size_t)gw * 64 + 2 * lane);
    float2 bb = *(const float2*)(b2 + 2 * lane);
    float2 r;
    r.x = ax * inv + q.x + bb.x;
    r.y = ay * inv + q.y + bb.y;
    *(float2*)(out + (size_t)gw * 64 + 2 * lane) = r;

    // prep next run (deterministic across replays)
    if (lane == 0) d_deg[gw] = 0;
    if (blockIdx.x == 0 && threadIdx.x < 128) {
        d_bsums[threadIdx.x] = 0;
        d_bflag[threadIdx.x] = 0;
        if (threadIdx.x == 0) d_barrier = 0;
    }
}

// ---------------------------------------------------------------------------
// 4) fused fp16 m16n8k16 GEMM. BM=128, BN=128, BK=32 halves, 512 threads,
// 16 warps, warp tile 32x32, 3-stage cp.async pipeline (ONE sync per ktile),
// ldmatrix fragments.  (R12/R14-winning version, unchanged.)
//  phase1: acc = [agg16 | x16](K=256) @ W1c; h1 = relu(acc+b1) -> fp16 smem
//  phase2: [p|q] = h1(K=128) @ W2c; p -> fp16 d_p16, q -> fp32 d_q
// smem: 3 stages x (A 10240B + B 10240B) = 61440B, then A2 34816B.
// ---------------------------------------------------------------------------

#define AST   20
#define BST   20
#define A2ST  68
#define STGB  20480
#define BOFF  10240
#define A2_B  61440
#define SMEM_BYTES (A2_B + 128 * A2ST * 4)   // 96256

__device__ __forceinline__ void mma_f16(float c[4],
                                        uint32_t a0, uint32_t a1, uint32_t a2, uint32_t a3,
                                        uint32_t b0, uint32_t b1) {
    asm volatile(
        "mma.sync.aligned.m16n8k16.row.col.f32.f16.f16.f32 "
        "{%0,%1,%2,%3},{%4,%5,%6,%7},{%8,%9},{%0,%1,%2,%3};"
        : "+f"(c[0]), "+f"(c[1]), "+f"(c[2]), "+f"(c[3])
        : "r"(a0), "r"(a1), "r"(a2), "r"(a3), "r"(b0), "r"(b1));
}

__device__ __forceinline__ void ldsm_x4(uint32_t& r0, uint32_t& r1,
                                        uint32_t& r2, uint32_t& r3, uint32_t addr) {
    asm volatile("ldmatrix.sync.aligned.m8n8.x4.shared.b16 {%0,%1,%2,%3}, [%4];"
                 : "=r"(r0), "=r"(r1), "=r"(r2), "=r"(r3) : "r"(addr));
}

__device__ __forceinline__ void cp16(uint32_t dst, const void* src, int sz) {
    asm volatile("cp.async.cg.shared.global [%0], [%1], 16, %2;"
                 :: "r"(dst), "l"(src), "r"(sz) : "memory");
}
#define CP_COMMIT() asm volatile("cp.async.commit_group;" ::: "memory")
#define CP_WAIT0()  asm volatile("cp.async.wait_group 0;" ::: "memory")
#define CP_WAIT1()  asm volatile("cp.async.wait_group 1;" ::: "memory")

__global__ __launch_bounds__(512, 2) void k_fused(const float* __restrict__ b1, int M) {
    extern __shared__ uint32_t smem[];
    const uint32_t sb = (uint32_t)__cvta_generic_to_shared(smem);

    const int tid = threadIdx.x;
    const int lane = tid & 31;
    const int warp = tid >> 5;
    const int wm = warp >> 2;          // 0..3: 32-row band
    const int wn = warp & 3;           // 0..3: 32-col band
    const int g = lane >> 2;
    const int t = lane & 3;
    const int row0 = blockIdx.x * 128;

    // ldmatrix lane-address components (verified mapping)
    const int arow = lane & 15;
    const int acolw = (lane >> 4) * 4;
    const int brow = (lane & 7) + ((lane >= 16) ? 8 : 0);
    const int bcolw = ((lane & 15) >= 8) ? 4 : 0;

    // cp.async coords: 512 threads cover 128 rows x 4 uint4
    const int ldrow = tid >> 2;
    const int ldc4 = tid & 3;
    const int grow = row0 + ldrow;
    const int avalid = (grow < M) ? 16 : 0;
    const size_t arowoff = (size_t)((grow < M) ? grow : 0) * 16;

    const uint4* agg4 = (const uint4*)d_agg16;
    const uint4* x4   = (const uint4*)d_x16;
    const uint4* w1   = (const uint4*)d_w1c;   // 32 uint4 per n
    const uint4* w2   = (const uint4*)d_w2c;   // 16 uint4 per n

    const uint32_t a_dst = sb + (uint32_t)(ldrow * AST + ldc4 * 4) * 4;
    const uint32_t b_dst = sb + BOFF + (uint32_t)(ldrow * BST + ldc4 * 4) * 4;

    float acc[2][4][4];
#pragma unroll
    for (int mi = 0; mi < 2; mi++)
#pragma unroll
        for (int ni = 0; ni < 4; ni++)
#pragma unroll
            for (int r = 0; r < 4; r++) acc[mi][ni][r] = 0.f;

    auto mma_tiles = [&](uint32_t aBase, int astride, int kof, uint32_t bBase) {
#pragma unroll
        for (int ks = 0; ks < 2; ks++) {
            uint32_t a[2][4];
#pragma unroll
            for (int mi = 0; mi < 2; mi++) {
                uint32_t addr = aBase +
                    (uint32_t)(((wm * 32 + mi * 16 + arow) * astride) +
                               kof + ks * 8 + acolw) * 4;
                ldsm_x4(a[mi][0], a[mi][1], a[mi][2], a[mi][3], addr);
            }
            uint32_t bf[2][4];
#pragma unroll
            for (int pr = 0; pr < 2; pr++) {
                uint32_t addr = bBase +
                    (uint32_t)(((wn * 32 + pr * 16 + brow) * BST) +
                               ks * 8 + bcolw) * 4;
                ldsm_x4(bf[pr][0], bf[pr][1], bf[pr][2], bf[pr][3], addr);
            }
#pragma unroll
            for (int mi = 0; mi < 2; mi++)
#pragma unroll
                for (int ni = 0; ni < 4; ni++)
                    mma_f16(acc[mi][ni], a[mi][0], a[mi][1], a[mi][2], a[mi][3],
                            bf[ni >> 1][(ni & 1) * 2], bf[ni >> 1][(ni & 1) * 2 + 1]);
        }
    };

    auto loadA1 = [&](int kt, uint32_t stg) {
        const uint4* src = (kt < 4) ? (agg4 + arowoff + kt * 4 + ldc4)
                                    : (x4 + arowoff + (kt - 4) * 4 + ldc4);
        cp16(a_dst + stg * STGB, src, avalid);
    };
    auto loadB1 = [&](int kt, uint32_t stg) {
        cp16(b_dst + stg * STGB, w1 + ldrow * 32 + kt * 4 + ldc4, 16);
    };
    auto loadB2 = [&](int kt, uint32_t stg) {
        cp16(b_dst + stg * STGB, w2 + ldrow * 16 + kt * 4 + ldc4, 16);
    };

    // ----- phase 1: K = 256, 8 ktiles, 3-stage, 1 sync/ktile -----
    loadA1(0, 0); loadB1(0, 0); CP_COMMIT();
    loadA1(1, 1); loadB1(1, 1); CP_COMMIT();
#pragma unroll
    for (int kt = 0; kt < 8; kt++) {
        if (kt < 7) CP_WAIT1(); else CP_WAIT0();
        __syncthreads();
        if (kt + 2 < 8) {
            loadA1(kt + 2, (kt + 2) % 3);
            loadB1(kt + 2, (kt + 2) % 3);
            CP_COMMIT();
        }
        const uint32_t s = (kt % 3) * STGB;
        mma_tiles(sb + s, AST, 0, sb + BOFF + s);
    }

    __syncthreads();

    // prefetch W2 ktiles 0,1 into B stages 0,1 (overlaps epilogue)
    loadB2(0, 0); CP_COMMIT();
    loadB2(1, 1); CP_COMMIT();

    // phase-1 epilogue: h1 = relu(acc + b1) -> fp16 A2 (k-paired)
    {
        uint32_t* A2w = smem + A2_B / 4;
#pragma unroll
        for (int mi = 0; mi < 2; mi++) {
#pragma unroll
            for (int ni = 0; ni < 4; ni++) {
                int rr = wm * 32 + mi * 16 + g;
                int cc = wn * 32 + ni * 8 + 2 * t;
                int ci = cc >> 1;
                float bb0 = b1[cc], bb1 = b1[cc + 1];
                __half2 h0 = __floats2half2_rn(fmaxf(acc[mi][ni][0] + bb0, 0.f),
                                               fmaxf(acc[mi][ni][1] + bb1, 0.f));
                __half2 h1 = __floats2half2_rn(fmaxf(acc[mi][ni][2] + bb0, 0.f),
                                               fmaxf(acc[mi][ni][3] + bb1, 0.f));
                A2w[rr * A2ST + ci] = *(const uint32_t*)&h0;
                A2w[(rr + 8) * A2ST + ci] = *(const uint32_t*)&h1;
            }
        }
    }
#pragma unroll
    for (int mi = 0; mi < 2; mi++)
#pragma unroll
        for (int ni = 0; ni < 4; ni++)
#pragma unroll
            for (int r = 0; r < 4; r++) acc[mi][ni][r] = 0.f;

    // ----- phase 2: K = 128, 4 ktiles, A2 resident, B 3-stage, 1 sync/kt -----
#pragma unroll
    for (int kt = 0; kt < 4; kt++) {
        if (kt < 3) CP_WAIT1(); else CP_WAIT0();
        __syncthreads();                     // also orders A2 writes (kt==0)
        if (kt + 2 < 4) { loadB2(kt + 2, (kt + 2) % 3); CP_COMMIT(); }
        mma_tiles(sb + A2_B, A2ST, kt * 16, sb + BOFF + (kt % 3) * STGB);
    }

    // phase-2 epilogue: cols < 64 -> p fp16; cols >= 64 -> q fp32
#pragma unroll
    for (int mi = 0; mi < 2; mi++) {
#pragma unroll
        for (int ni = 0; ni < 4; ni++) {
            int r0 = row0 + wm * 32 + mi * 16 + g;
            int cc = wn * 32 + ni * 8 + 2 * t;
            if (cc < 64) {
                __half2 h0 = __floats2half2_rn(acc[mi][ni][0], acc[mi][ni][1]);
                __half2 h1 = __floats2half2_rn(acc[mi][ni][2], acc[mi][ni][3]);
                if (r0 < M)
                    *(__half2*)(d_p16 + (size_t)r0 * 64 + cc) = h0;
                if (r0 + 8 < M)
                    *(__half2*)(d_p16 + (size_t)(r0 + 8) * 64 + cc) = h1;
            } else {
                int cq = cc - 64;
                if (r0 < M)
                    *(float2*)(d_q + (size_t)r0 * 64 + cq) =
                        make_float2(acc[mi][ni][0], acc[mi][ni][1]);
                if (r0 + 8 < M)
                    *(float2*)(d_q + (size_t)(r0 + 8) * 64 + cq) =
                        make_float2(acc[mi][ni][2], acc[mi][ni][3]);
            }
        }
    }
}

// ---------------------------------------------------------------------------
// Launch
// ---------------------------------------------------------------------------

extern "C" void kernel_launch(void* const* d_in, const int* in_sizes, int n_in,
                              void* d_out, int out_size) {
    const float* x   = (const float*)d_in[0];
    const void*  ei  = d_in[1];
    const float* Wl1 = (const float*)d_in[2];
    const float* Wr1 = (const float*)d_in[3];
    const float* b1  = (const float*)d_in[4];
    const float* Wl2 = (const float*)d_in[5];
    const float* Wr2 = (const float*)d_in[6];
    const float* b2  = (const float*)d_in[7];
    float* out = (float*)d_out;

    int n = in_sizes[0] / 128;
    int E = in_sizes[1] / 2;

    static int smem_set = 0;
    if (!smem_set) {
        cudaFuncSetAttribute(k_fused, cudaFuncAttributeMaxDynamicSharedMemorySize,
                             SMEM_BYTES);
        smem_set = 1;
    }

    int nb = (n + SCAN_BLK - 1) / SCAN_BLK;

    k_prehist<<<(n * 32 + 255) / 256, 256>>>(x, ei, Wl1, Wr1, Wl2, Wr2, n, E);
    k_scan_scatter<<<nb, SCAN_BLK>>>(ei, n, E);
    k_agg16<<<(n * 32 + 255) / 256, 256>>>(n);
    k_fused<<<(n + 127) / 128, 512, SMEM_BYTES>>>(b1, n);     // launch 4 (profiled)
    k_final16<<<(n * 32 + 255) / 256, 256>>>(out, b2, n);
}